// round 4
// baseline (speedup 1.0000x reference)
#include <cuda_runtime.h>
#include <cstdint>

#define N_NODES 100000
#define N_EDGES 3200000
#define F_IN    1433
#define F_HID   16
#define F_OUT   7

#define KPAD     1472                 // F_IN padded to multiple of 64
#define KSTEP    64
#define NSTAGES  (KPAD / KSTEP)       // 23
#define PSTAGE   5                    // cp.async ring depth
#define TILE_M   64
#define N_TILES  ((N_NODES + TILE_M - 1) / TILE_M)   // 1563
#define G1_GRID  148
#define G1_THREADS 512

#define SMEM_W_BYTES (8 * KPAD * 8)               // 94208
#define SMEM_X_BYTES (PSTAGE * TILE_M * KSTEP * 4) // 81920
#define G1_SMEM      (SMEM_W_BYTES + SMEM_X_BYTES) // 176128

// ---------------- scratch (device globals; no allocation allowed) ----------
__device__ float g_h1  [N_NODES * F_HID];
__device__ float g_agg1[N_NODES * F_HID];
__device__ float g_h2  [N_NODES * 8];
__device__ float g_agg2[N_NODES * 8];
__device__ float g_degout[N_NODES];
__device__ float g_degin [N_NODES];
__device__ float g_ns[N_NODES];
__device__ float g_nd[N_NODES];

__device__ __forceinline__ void red_add_v4(float* p, float4 v) {
    asm volatile("red.global.add.v4.f32 [%0], {%1, %2, %3, %4};"
                 :: "l"(p), "f"(v.x), "f"(v.y), "f"(v.z), "f"(v.w)
                 : "memory");
}

// ---- packed f32x2 helpers (sm_103a FFMA2 — PTX-only form) ------------------
__device__ __forceinline__ unsigned long long fma2(unsigned long long a,
                                                   unsigned long long b,
                                                   unsigned long long c) {
    unsigned long long d;
    asm("fma.rn.f32x2 %0, %1, %2, %3;" : "=l"(d) : "l"(a), "l"(b), "l"(c));
    return d;
}
__device__ __forceinline__ unsigned long long add2(unsigned long long a,
                                                   unsigned long long b) {
    unsigned long long d;
    asm("add.rn.f32x2 %0, %1, %2;" : "=l"(d) : "l"(a), "l"(b));
    return d;
}
__device__ __forceinline__ unsigned long long splat2(float x) {
    unsigned long long d;
    asm("mov.b64 %0, {%1, %1};" : "=l"(d) : "f"(x));
    return d;
}
__device__ __forceinline__ float2 unpack2(unsigned long long v) {
    float2 r;
    asm("mov.b64 {%0, %1}, %2;" : "=f"(r.x), "=f"(r.y) : "l"(v));
    return r;
}
__device__ __forceinline__ void cp_async4(uint32_t dst, const float* src, int src_sz) {
    asm volatile("cp.async.ca.shared.global [%0], [%1], 4, %2;"
                 :: "r"(dst), "l"(src), "r"(src_sz));
}
__device__ __forceinline__ void cp_commit() {
    asm volatile("cp.async.commit_group;");
}
template <int N>
__device__ __forceinline__ void cp_wait() {
    asm volatile("cp.async.wait_group %0;" :: "n"(N));
}

// ---------------- zeroing (graph-replay safe) -------------------------------
__global__ void zero_kernel() {
    int t = blockIdx.x * blockDim.x + threadIdx.x;
    float4 z = make_float4(0.f, 0.f, 0.f, 0.f);
    if (t < N_NODES * F_HID / 4) ((float4*)g_agg1)[t] = z;
    if (t < N_NODES * 8 / 4)     ((float4*)g_agg2)[t] = z;
    if (t < N_NODES) { g_degout[t] = 0.f; g_degin[t] = 0.f; }
}

// ---------------- degrees + norms -------------------------------------------
__global__ void degree_kernel(const int* __restrict__ src,
                              const int* __restrict__ dst) {
    int e = blockIdx.x * blockDim.x + threadIdx.x;
    if (e >= N_EDGES) return;
    atomicAdd(&g_degout[src[e]], 1.0f);
    atomicAdd(&g_degin [dst[e]], 1.0f);
}

__global__ void norm_kernel() {
    int n = blockIdx.x * blockDim.x + threadIdx.x;
    if (n >= N_NODES) return;
    g_ns[n] = rsqrtf(fmaxf(g_degout[n], 1.0f));
    g_nd[n] = rsqrtf(fmaxf(g_degin [n], 1.0f));
}

// ---------------- GEMM1: h1 = diag(ns) * X @ W1  -----------------------------
// W1 in smem (transposed, pair-packed). X staged through a 5-deep cp.async
// ring (16 KB/stage); zfill handles both K tail and M tail. 16 warps/SM,
// each owning 4 rows, lanes splitting K. Latency lives in the cp.async ring,
// not in registers.
__global__ __launch_bounds__(G1_THREADS) void gemm1_kernel(const float* __restrict__ X,
                                                           const float* __restrict__ W) {
    extern __shared__ char smem_[];
    unsigned long long* sWp = (unsigned long long*)smem_;          // [8][KPAD]
    float* sX = (float*)(smem_ + SMEM_W_BYTES);                    // [PSTAGE][64][64]
    uint32_t sX_u32 = (uint32_t)__cvta_generic_to_shared(sX);

    // stage W: read as float2 (coalesced), write transposed+packed
    const float2* Wv = (const float2*)W;                            // Wv[k*8 + p]
    for (int idx = threadIdx.x; idx < 8 * KPAD; idx += G1_THREADS) {
        int k = idx >> 3, p = idx & 7;
        float2 v = (k < F_IN) ? Wv[k * 8 + p] : make_float2(0.f, 0.f);
        unsigned long long pk;
        asm("mov.b64 %0, {%1, %2};" : "=l"(pk) : "f"(v.x), "f"(v.y));
        sWp[p * KPAD + k] = pk;
    }
    __syncthreads();

    const int tid  = threadIdx.x;
    const int lane = tid & 31;
    const int warp = tid >> 5;

    for (int tile = blockIdx.x; tile < N_TILES; tile += G1_GRID) {
        const long m_base = (long)tile * TILE_M;

        // --- stage loader (all 512 threads): 8 x 4B cp.async per stage ------
        auto load_stage = [&](int kidx, int buf) {
            if (kidx >= NSTAGES) { cp_commit(); return; }
            int k0 = kidx * KSTEP;
            uint32_t dbase = sX_u32 + (uint32_t)(buf * TILE_M * KSTEP * 4);
#pragma unroll
            for (int j = 0; j < (TILE_M * KSTEP) / G1_THREADS; j++) {
                int e   = tid + j * G1_THREADS;
                int row = e >> 6;
                int kk  = e & 63;
                long m  = m_base + row;
                int  k  = k0 + kk;
                bool ok = (m < N_NODES) && (k < F_IN);
                const float* src = ok ? (X + m * F_IN + k) : X;
                cp_async4(dbase + (uint32_t)(e << 2), src, ok ? 4 : 0);
            }
            cp_commit();
        };

        // prologue: fill stages 0..PSTAGE-2
#pragma unroll
        for (int s = 0; s < PSTAGE - 1; s++) load_stage(s, s);

        unsigned long long acc[4][8];
#pragma unroll
        for (int i = 0; i < 4; i++)
#pragma unroll
            for (int p = 0; p < 8; p++) acc[i][p] = 0ull;

        const int r0 = warp * 4;

#pragma unroll 1
        for (int it = 0; it < NSTAGES; it++) {
            load_stage(it + PSTAGE - 1, (it + PSTAGE - 1) % PSTAGE);
            cp_wait<PSTAGE - 1>();          // stage `it` resident
            __syncthreads();

            const float* sXb = sX + (it % PSTAGE) * (TILE_M * KSTEP);
            const int kw = it * KSTEP;      // global k base for W

            // sub-block A (k = kw + lane)
            {
                unsigned long long xx[4];
#pragma unroll
                for (int i = 0; i < 4; i++) xx[i] = splat2(sXb[(r0 + i) * KSTEP + lane]);
                int k = kw + lane;
#pragma unroll
                for (int p = 0; p < 8; p++) {
                    unsigned long long w = sWp[p * KPAD + k];
#pragma unroll
                    for (int i = 0; i < 4; i++) acc[i][p] = fma2(xx[i], w, acc[i][p]);
                }
            }
            // sub-block B (k = kw + 32 + lane)
            {
                unsigned long long xx[4];
#pragma unroll
                for (int i = 0; i < 4; i++) xx[i] = splat2(sXb[(r0 + i) * KSTEP + 32 + lane]);
                int k = kw + 32 + lane;
#pragma unroll
                for (int p = 0; p < 8; p++) {
                    unsigned long long w = sWp[p * KPAD + k];
#pragma unroll
                    for (int i = 0; i < 4; i++) acc[i][p] = fma2(xx[i], w, acc[i][p]);
                }
            }
            __syncthreads();                // all reads of this buffer done
        }

        // butterfly reduce across lanes (packed adds)
#pragma unroll
        for (int off = 16; off > 0; off >>= 1)
#pragma unroll
            for (int i = 0; i < 4; i++)
#pragma unroll
                for (int p = 0; p < 8; p++)
                    acc[i][p] = add2(acc[i][p],
                                     __shfl_xor_sync(0xffffffffu, acc[i][p], off));

        if (lane == 0) {
#pragma unroll
            for (int i = 0; i < 4; i++) {
                long m = m_base + r0 + i;
                if (m < N_NODES) {
                    float s = g_ns[m];
                    float2* o = (float2*)(g_h1 + m * F_HID);
#pragma unroll
                    for (int p = 0; p < 8; p++) {
                        float2 v = unpack2(acc[i][p]);
                        o[p] = make_float2(v.x * s, v.y * s);
                    }
                }
            }
        }
        __syncthreads();   // ring buffers reused by next tile
    }
}

// ---------------- scatter 1: agg1[dst] += h1[src]  (16 wide) ----------------
__global__ void scatter1_kernel(const int* __restrict__ src,
                                const int* __restrict__ dst) {
    int e = blockIdx.x * blockDim.x + threadIdx.x;
    if (e >= N_EDGES) return;
    int s = src[e], d = dst[e];
    const float4* hs = (const float4*)(g_h1 + (size_t)s * F_HID);
    float4 a = hs[0], b = hs[1], c = hs[2], f = hs[3];
    float* base = g_agg1 + (size_t)d * F_HID;
    red_add_v4(base + 0,  a);
    red_add_v4(base + 4,  b);
    red_add_v4(base + 8,  c);
    red_add_v4(base + 12, f);
}

// ---------------- GEMM2: h2 = diag(ns) * relu(agg1*nd + b1) @ W2 ------------
__global__ void gemm2_kernel(const float* __restrict__ b1,
                             const float* __restrict__ W2) {
    __shared__ float sW[F_HID * F_OUT];
    __shared__ float sb[F_HID];
    if (threadIdx.x < F_HID * F_OUT) sW[threadIdx.x] = W2[threadIdx.x];
    if (threadIdx.x < F_HID)         sb[threadIdx.x] = b1[threadIdx.x];
    __syncthreads();

    int n = blockIdx.x * blockDim.x + threadIdx.x;
    if (n >= N_NODES) return;

    float ndv = g_nd[n], nsv = g_ns[n];
    const float4* a4 = (const float4*)(g_agg1 + (size_t)n * F_HID);
    float x[F_HID];
#pragma unroll
    for (int q = 0; q < 4; q++) {
        float4 v = a4[q];
        x[q*4+0] = v.x; x[q*4+1] = v.y; x[q*4+2] = v.z; x[q*4+3] = v.w;
    }
    float o[F_OUT];
#pragma unroll
    for (int j = 0; j < F_OUT; j++) o[j] = 0.f;
#pragma unroll
    for (int i = 0; i < F_HID; i++) {
        float xi = fmaxf(fmaf(x[i], ndv, sb[i]), 0.f) * nsv;
#pragma unroll
        for (int j = 0; j < F_OUT; j++) o[j] = fmaf(xi, sW[i * F_OUT + j], o[j]);
    }
    float4* hp = (float4*)(g_h2 + (size_t)n * 8);
    hp[0] = make_float4(o[0], o[1], o[2], o[3]);
    hp[1] = make_float4(o[4], o[5], o[6], 0.f);   // pad lane stays 0
}

// ---------------- scatter 2: agg2[dst] += h2[src]  (8 wide, padded) ---------
__global__ void scatter2_kernel(const int* __restrict__ src,
                                const int* __restrict__ dst) {
    int e = blockIdx.x * blockDim.x + threadIdx.x;
    if (e >= N_EDGES) return;
    int s = src[e], d = dst[e];
    const float4* hs = (const float4*)(g_h2 + (size_t)s * 8);
    float4 a = hs[0], b = hs[1];
    float* base = g_agg2 + (size_t)d * 8;
    red_add_v4(base + 0, a);
    red_add_v4(base + 4, b);
}

// ---------------- finalize: out = agg2*nd + b2 -------------------------------
__global__ void final_kernel(const float* __restrict__ b2,
                             float* __restrict__ out) {
    int t = blockIdx.x * blockDim.x + threadIdx.x;
    if (t >= N_NODES * F_OUT) return;
    int n = t / F_OUT;
    int j = t - n * F_OUT;
    out[t] = fmaf(g_agg2[(size_t)n * 8 + j], g_nd[n], b2[j]);
}

// ---------------- launch ------------------------------------------------------
extern "C" void kernel_launch(void* const* d_in, const int* in_sizes, int n_in,
                              void* d_out, int out_size) {
    const float* X   = (const float*)d_in[0];
    const int*   src = (const int*)  d_in[1];
    const int*   dst = (const int*)  d_in[2];
    const float* W1  = (const float*)d_in[3];
    const float* b1  = (const float*)d_in[4];
    const float* W2  = (const float*)d_in[5];
    const float* b2  = (const float*)d_in[6];
    float* out = (float*)d_out;

    static int attr_done = 0;
    if (!attr_done) {   // idempotent host-side attribute, not a capture op
        cudaFuncSetAttribute(gemm1_kernel,
                             cudaFuncAttributeMaxDynamicSharedMemorySize, G1_SMEM);
        attr_done = 1;
    }

    zero_kernel  <<<(N_NODES * F_HID / 4 + 255) / 256, 256>>>();
    degree_kernel<<<N_EDGES / 256, 256>>>(src, dst);
    norm_kernel  <<<(N_NODES + 255) / 256, 256>>>();
    gemm1_kernel <<<G1_GRID, G1_THREADS, G1_SMEM>>>(X, W1);
    scatter1_kernel<<<N_EDGES / 256, 256>>>(src, dst);
    gemm2_kernel <<<(N_NODES + 255) / 256, 256>>>(b1, W2);
    scatter2_kernel<<<N_EDGES / 256, 256>>>(src, dst);
    final_kernel <<<(N_NODES * F_OUT + 255) / 256, 256>>>(b2, out);
}

// round 5
// speedup vs baseline: 1.2699x; 1.2699x over previous
#include <cuda_runtime.h>
#include <cstdint>

#define N_NODES 100000
#define N_EDGES 3200000
#define F_IN    1433
#define F_HID   16
#define F_OUT   7

#define KPAD     1536            // F_IN padded to multiple of 128 (zero-filled W)
#define G1_GRID  296             // 148 SMs x 2 blocks
#define NCHUNK   (N_NODES / 4)   // 25000 4-row warp chunks

// ---------------- scratch (device globals; no allocation allowed) ----------
__device__ float g_h1  [N_NODES * F_HID];
__device__ float g_agg1[N_NODES * F_HID];
__device__ float g_h2  [N_NODES * 8];
__device__ float g_agg2[N_NODES * 8];
__device__ float g_degout[N_NODES];
__device__ float g_degin [N_NODES];
__device__ float g_ns[N_NODES];
__device__ float g_nd[N_NODES];

__device__ __forceinline__ void red_add_v4(float* p, float4 v) {
    asm volatile("red.global.add.v4.f32 [%0], {%1, %2, %3, %4};"
                 :: "l"(p), "f"(v.x), "f"(v.y), "f"(v.z), "f"(v.w)
                 : "memory");
}

// ---- packed f32x2 helpers (sm_103a FFMA2 — PTX-only form) ------------------
__device__ __forceinline__ unsigned long long fma2(unsigned long long a,
                                                   unsigned long long b,
                                                   unsigned long long c) {
    unsigned long long d;
    asm("fma.rn.f32x2 %0, %1, %2, %3;" : "=l"(d) : "l"(a), "l"(b), "l"(c));
    return d;
}
__device__ __forceinline__ unsigned long long add2(unsigned long long a,
                                                   unsigned long long b) {
    unsigned long long d;
    asm("add.rn.f32x2 %0, %1, %2;" : "=l"(d) : "l"(a), "l"(b));
    return d;
}
__device__ __forceinline__ unsigned long long splat2(float x) {
    unsigned long long d;
    asm("mov.b64 %0, {%1, %1};" : "=l"(d) : "f"(x));
    return d;
}
__device__ __forceinline__ float2 unpack2(unsigned long long v) {
    float2 r;
    asm("mov.b64 {%0, %1}, %2;" : "=f"(r.x), "=f"(r.y) : "l"(v));
    return r;
}
__device__ __forceinline__ float ldcs(const float* p) {
    float v;
    asm("ld.global.cs.f32 %0, [%1];" : "=f"(v) : "l"(p));
    return v;
}

// ---------------- zeroing (graph-replay safe) -------------------------------
__global__ void zero_kernel() {
    int t = blockIdx.x * blockDim.x + threadIdx.x;
    float4 z = make_float4(0.f, 0.f, 0.f, 0.f);
    if (t < N_NODES * F_HID / 4) ((float4*)g_agg1)[t] = z;
    if (t < N_NODES * 8 / 4)     ((float4*)g_agg2)[t] = z;
    if (t < N_NODES) { g_degout[t] = 0.f; g_degin[t] = 0.f; }
}

// ---------------- degrees + norms -------------------------------------------
__global__ void degree_kernel(const int* __restrict__ src,
                              const int* __restrict__ dst) {
    int e = blockIdx.x * blockDim.x + threadIdx.x;
    if (e >= N_EDGES) return;
    atomicAdd(&g_degout[src[e]], 1.0f);
    atomicAdd(&g_degin [dst[e]], 1.0f);
}

__global__ void norm_kernel() {
    int n = blockIdx.x * blockDim.x + threadIdx.x;
    if (n >= N_NODES) return;
    g_ns[n] = rsqrtf(fmaxf(g_degout[n], 1.0f));
    g_nd[n] = rsqrtf(fmaxf(g_degin [n], 1.0f));
}

// ---------------- GEMM1: h1 = diag(ns) * X @ W1  -----------------------------
// W1 in smem, transposed + pair-packed, zero-padded to KPAD. Each warp owns
// 4 rows; lanes split K. Ping-pong register prefetch (manually 2x-unrolled:
// no buffer copies, compile-time indices). X column index clamped instead of
// predicated: k>=F_IN reads a valid-but-garbage element, multiplied by W=0.
__global__ __launch_bounds__(256, 2) void gemm1_kernel(const float* __restrict__ X,
                                                       const float* __restrict__ W) {
    extern __shared__ unsigned long long sWp[];   // [8][KPAD] packed float2

    // stage W: read as float2 (coalesced), write transposed+packed, pad zeros
    const float2* Wv = (const float2*)W;          // Wv[k*8 + p]
    for (int idx = threadIdx.x; idx < 8 * KPAD; idx += 256) {
        int k = idx >> 3, p = idx & 7;
        float2 v = (k < F_IN) ? Wv[k * 8 + p] : make_float2(0.f, 0.f);
        unsigned long long pk;
        asm("mov.b64 %0, {%1, %2};" : "=l"(pk) : "f"(v.x), "f"(v.y));
        sWp[p * KPAD + k] = pk;
    }
    __syncthreads();

    const int lane = threadIdx.x & 31;
    const int gw   = blockIdx.x * 8 + (threadIdx.x >> 5);

    for (int chunk = gw; chunk < NCHUNK; chunk += G1_GRID * 8) {
        const long m0 = (long)chunk * 4;
        const float* Xr = X + m0 * F_IN;

        unsigned long long acc[4][8];
#pragma unroll
        for (int i = 0; i < 4; i++)
#pragma unroll
            for (int p = 0; p < 8; p++) acc[i][p] = 0ull;

        float Axa[4], Axb[4];   // buffer A
        float Bxa[4], Bxb[4];   // buffer B

        // preload block 0 -> A  (block 0 columns always valid)
#pragma unroll
        for (int i = 0; i < 4; i++) {
            Axa[i] = ldcs(Xr + (long)i * F_IN + lane);
            Axb[i] = ldcs(Xr + (long)i * F_IN + 32 + lane);
        }

        // compute one 64-k block: x in (xa, xb), W at k0
#define COMPUTE_BLOCK(k0v, xa, xb)                                            \
        {                                                                     \
            const int kA = (k0v) + lane;                                      \
            unsigned long long xx[4];                                         \
            _Pragma("unroll")                                                 \
            for (int i = 0; i < 4; i++) xx[i] = splat2(xa[i]);                \
            _Pragma("unroll")                                                 \
            for (int p = 0; p < 8; p++) {                                     \
                unsigned long long w = sWp[p * KPAD + kA];                    \
                _Pragma("unroll")                                             \
                for (int i = 0; i < 4; i++) acc[i][p] = fma2(xx[i], w, acc[i][p]); \
            }                                                                 \
            const int kB = (k0v) + 32 + lane;                                 \
            _Pragma("unroll")                                                 \
            for (int i = 0; i < 4; i++) xx[i] = splat2(xb[i]);                \
            _Pragma("unroll")                                                 \
            for (int p = 0; p < 8; p++) {                                     \
                unsigned long long w = sWp[p * KPAD + kB];                    \
                _Pragma("unroll")                                             \
                for (int i = 0; i < 4; i++) acc[i][p] = fma2(xx[i], w, acc[i][p]); \
            }                                                                 \
        }

        // prefetch a 64-k block (clamped columns) into (xa, xb)
#define PREFETCH_BLOCK(k0v, xa, xb)                                           \
        {                                                                     \
            const int ka = min((k0v) + lane,      F_IN - 1);                  \
            const int kb = min((k0v) + 32 + lane, F_IN - 1);                  \
            _Pragma("unroll")                                                 \
            for (int i = 0; i < 4; i++) {                                     \
                xa[i] = ldcs(Xr + (long)i * F_IN + ka);                       \
                xb[i] = ldcs(Xr + (long)i * F_IN + kb);                       \
            }                                                                 \
        }

        // 24 blocks, processed in 12 ping-pong pairs. The final prefetch
        // (block 24) is out of range but clamped & never used.
#pragma unroll 1
        for (int it2 = 0; it2 < 12; it2++) {
            const int kb0 = it2 * 128;
            PREFETCH_BLOCK(kb0 + 64, Bxa, Bxb);   // block 2*it2+1 -> B
            COMPUTE_BLOCK (kb0,      Axa, Axb);   // block 2*it2   (A)
            PREFETCH_BLOCK(kb0 + 128, Axa, Axb);  // block 2*it2+2 -> A
            COMPUTE_BLOCK (kb0 + 64, Bxa, Bxb);   // block 2*it2+1 (B)
        }
#undef COMPUTE_BLOCK
#undef PREFETCH_BLOCK

        // butterfly reduce across lanes (packed adds)
#pragma unroll
        for (int off = 16; off > 0; off >>= 1)
#pragma unroll
            for (int i = 0; i < 4; i++)
#pragma unroll
                for (int p = 0; p < 8; p++)
                    acc[i][p] = add2(acc[i][p],
                                     __shfl_xor_sync(0xffffffffu, acc[i][p], off));

        if (lane == 0) {
#pragma unroll
            for (int i = 0; i < 4; i++) {
                float s = g_ns[m0 + i];
                float2* o = (float2*)(g_h1 + (m0 + i) * F_HID);
#pragma unroll
                for (int p = 0; p < 8; p++) {
                    float2 v = unpack2(acc[i][p]);
                    o[p] = make_float2(v.x * s, v.y * s);
                }
            }
        }
    }
}

// ---------------- scatter 1: agg1[dst] += h1[src]  (16 wide) ----------------
__global__ void scatter1_kernel(const int* __restrict__ src,
                                const int* __restrict__ dst) {
    int e = blockIdx.x * blockDim.x + threadIdx.x;
    if (e >= N_EDGES) return;
    int s = src[e], d = dst[e];
    const float4* hs = (const float4*)(g_h1 + (size_t)s * F_HID);
    float4 a = hs[0], b = hs[1], c = hs[2], f = hs[3];
    float* base = g_agg1 + (size_t)d * F_HID;
    red_add_v4(base + 0,  a);
    red_add_v4(base + 4,  b);
    red_add_v4(base + 8,  c);
    red_add_v4(base + 12, f);
}

// ---------------- GEMM2: h2 = diag(ns) * relu(agg1*nd + b1) @ W2 ------------
__global__ void gemm2_kernel(const float* __restrict__ b1,
                             const float* __restrict__ W2) {
    __shared__ float sW[F_HID * F_OUT];
    __shared__ float sb[F_HID];
    if (threadIdx.x < F_HID * F_OUT) sW[threadIdx.x] = W2[threadIdx.x];
    if (threadIdx.x < F_HID)         sb[threadIdx.x] = b1[threadIdx.x];
    __syncthreads();

    int n = blockIdx.x * blockDim.x + threadIdx.x;
    if (n >= N_NODES) return;

    float ndv = g_nd[n], nsv = g_ns[n];
    const float4* a4 = (const float4*)(g_agg1 + (size_t)n * F_HID);
    float x[F_HID];
#pragma unroll
    for (int q = 0; q < 4; q++) {
        float4 v = a4[q];
        x[q*4+0] = v.x; x[q*4+1] = v.y; x[q*4+2] = v.z; x[q*4+3] = v.w;
    }
    float o[F_OUT];
#pragma unroll
    for (int j = 0; j < F_OUT; j++) o[j] = 0.f;
#pragma unroll
    for (int i = 0; i < F_HID; i++) {
        float xi = fmaxf(fmaf(x[i], ndv, sb[i]), 0.f) * nsv;
#pragma unroll
        for (int j = 0; j < F_OUT; j++) o[j] = fmaf(xi, sW[i * F_OUT + j], o[j]);
    }
    float4* hp = (float4*)(g_h2 + (size_t)n * 8);
    hp[0] = make_float4(o[0], o[1], o[2], o[3]);
    hp[1] = make_float4(o[4], o[5], o[6], 0.f);   // pad lane stays 0
}

// ---------------- scatter 2: agg2[dst] += h2[src]  (8 wide, padded) ---------
__global__ void scatter2_kernel(const int* __restrict__ src,
                                const int* __restrict__ dst) {
    int e = blockIdx.x * blockDim.x + threadIdx.x;
    if (e >= N_EDGES) return;
    int s = src[e], d = dst[e];
    const float4* hs = (const float4*)(g_h2 + (size_t)s * 8);
    float4 a = hs[0], b = hs[1];
    float* base = g_agg2 + (size_t)d * 8;
    red_add_v4(base + 0, a);
    red_add_v4(base + 4, b);
}

// ---------------- finalize: out = agg2*nd + b2 -------------------------------
__global__ void final_kernel(const float* __restrict__ b2,
                             float* __restrict__ out) {
    int t = blockIdx.x * blockDim.x + threadIdx.x;
    if (t >= N_NODES * F_OUT) return;
    int n = t / F_OUT;
    int j = t - n * F_OUT;
    out[t] = fmaf(g_agg2[(size_t)n * 8 + j], g_nd[n], b2[j]);
}

// ---------------- launch ------------------------------------------------------
extern "C" void kernel_launch(void* const* d_in, const int* in_sizes, int n_in,
                              void* d_out, int out_size) {
    const float* X   = (const float*)d_in[0];
    const int*   src = (const int*)  d_in[1];
    const int*   dst = (const int*)  d_in[2];
    const float* W1  = (const float*)d_in[3];
    const float* b1  = (const float*)d_in[4];
    const float* W2  = (const float*)d_in[5];
    const float* b2  = (const float*)d_in[6];
    float* out = (float*)d_out;

    const int g1_smem = 8 * KPAD * 8;   // 98304 bytes
    static int attr_done = 0;
    if (!attr_done) {   // idempotent host-side attribute, not a capture op
        cudaFuncSetAttribute(gemm1_kernel,
                             cudaFuncAttributeMaxDynamicSharedMemorySize, g1_smem);
        attr_done = 1;
    }

    zero_kernel  <<<(N_NODES * F_HID / 4 + 255) / 256, 256>>>();
    degree_kernel<<<N_EDGES / 256, 256>>>(src, dst);
    norm_kernel  <<<(N_NODES + 255) / 256, 256>>>();
    gemm1_kernel <<<G1_GRID, 256, g1_smem>>>(X, W1);
    scatter1_kernel<<<N_EDGES / 256, 256>>>(src, dst);
    gemm2_kernel <<<(N_NODES + 255) / 256, 256>>>(b1, W2);
    scatter2_kernel<<<N_EDGES / 256, 256>>>(src, dst);
    final_kernel <<<(N_NODES * F_OUT + 255) / 256, 256>>>(b2, out);
}

// round 6
// speedup vs baseline: 1.3879x; 1.0929x over previous
#include <cuda_runtime.h>
#include <cstdint>

#define N_NODES 100000
#define N_EDGES 3200000
#define F_IN    1433
#define F_HID   16
#define F_OUT   7

#define KPAD     1536            // F_IN padded to multiple of 128 (zero-filled W)
#define G1_GRID  296             // 148 SMs x 2 blocks
#define NCHUNK   (N_NODES / 4)   // 25000 4-row warp chunks

// ---------------- scratch (device globals; no allocation allowed) ----------
__device__ float g_h1  [N_NODES * F_HID];
__device__ float g_agg1[N_NODES * F_HID];
__device__ float g_h2  [N_NODES * 8];
__device__ float g_agg2[N_NODES * 8];
__device__ float g_degout[N_NODES];
__device__ float g_degin [N_NODES];
__device__ float g_ns[N_NODES];
__device__ float g_nd[N_NODES];

__device__ __forceinline__ void red_add_v4(float* p, float4 v) {
    asm volatile("red.global.add.v4.f32 [%0], {%1, %2, %3, %4};"
                 :: "l"(p), "f"(v.x), "f"(v.y), "f"(v.z), "f"(v.w)
                 : "memory");
}

// ---- packed f32x2 helpers (sm_103a FFMA2 — PTX-only form) ------------------
__device__ __forceinline__ unsigned long long fma2(unsigned long long a,
                                                   unsigned long long b,
                                                   unsigned long long c) {
    unsigned long long d;
    asm("fma.rn.f32x2 %0, %1, %2, %3;" : "=l"(d) : "l"(a), "l"(b), "l"(c));
    return d;
}
__device__ __forceinline__ unsigned long long add2(unsigned long long a,
                                                   unsigned long long b) {
    unsigned long long d;
    asm("add.rn.f32x2 %0, %1, %2;" : "=l"(d) : "l"(a), "l"(b));
    return d;
}
__device__ __forceinline__ unsigned long long splat2(float x) {
    unsigned long long d;
    asm("mov.b64 %0, {%1, %1};" : "=l"(d) : "f"(x));
    return d;
}
__device__ __forceinline__ float2 unpack2(unsigned long long v) {
    float2 r;
    asm("mov.b64 {%0, %1}, %2;" : "=f"(r.x), "=f"(r.y) : "l"(v));
    return r;
}
__device__ __forceinline__ float ldcs(const float* p) {
    float v;
    asm("ld.global.cs.f32 %0, [%1];" : "=f"(v) : "l"(p));
    return v;
}

// ---------------- zeroing (graph-replay safe) -------------------------------
__global__ void zero_kernel() {
    int t = blockIdx.x * blockDim.x + threadIdx.x;
    float4 z = make_float4(0.f, 0.f, 0.f, 0.f);
    if (t < N_NODES * F_HID / 4) ((float4*)g_agg1)[t] = z;
    if (t < N_NODES * 8 / 4)     ((float4*)g_agg2)[t] = z;
    if (t < N_NODES) { g_degout[t] = 0.f; g_degin[t] = 0.f; }
}

// ---------------- degrees + norms -------------------------------------------
__global__ void degree_kernel(const int* __restrict__ src,
                              const int* __restrict__ dst) {
    int e = blockIdx.x * blockDim.x + threadIdx.x;
    if (e >= N_EDGES) return;
    atomicAdd(&g_degout[src[e]], 1.0f);
    atomicAdd(&g_degin [dst[e]], 1.0f);
}

__global__ void norm_kernel() {
    int n = blockIdx.x * blockDim.x + threadIdx.x;
    if (n >= N_NODES) return;
    g_ns[n] = rsqrtf(fmaxf(g_degout[n], 1.0f));
    g_nd[n] = rsqrtf(fmaxf(g_degin [n], 1.0f));
}

// ---------------- GEMM1: h1 = diag(ns) * X @ W1  -----------------------------
// W1 in smem, transposed + pair-packed, zero-padded to KPAD. Each warp owns
// 4 rows; lanes split K. 3-buffer register prefetch (distance-2, manually
// unrolled x3 -> compile-time buffer indices, no copies). X columns clamped
// (k >= F_IN reads a valid-but-garbage element, multiplied by W = 0).
// Epilogue: transpose-reduce (31 shfl) leaving one acc per lane, coalesced
// 32-lane STG.64.
__global__ __launch_bounds__(256, 2) void gemm1_kernel(const float* __restrict__ X,
                                                       const float* __restrict__ W) {
    extern __shared__ unsigned long long sWp[];   // [8][KPAD] packed float2

    // stage W: read as float2 (coalesced), write transposed+packed, pad zeros
    const float2* Wv = (const float2*)W;          // Wv[k*8 + p]
    for (int idx = threadIdx.x; idx < 8 * KPAD; idx += 256) {
        int k = idx >> 3, p = idx & 7;
        float2 v = (k < F_IN) ? Wv[k * 8 + p] : make_float2(0.f, 0.f);
        unsigned long long pk;
        asm("mov.b64 %0, {%1, %2};" : "=l"(pk) : "f"(v.x), "f"(v.y));
        sWp[p * KPAD + k] = pk;
    }
    __syncthreads();

    const int lane = threadIdx.x & 31;
    const int gw   = blockIdx.x * 8 + (threadIdx.x >> 5);

    for (int chunk = gw; chunk < NCHUNK; chunk += G1_GRID * 8) {
        const unsigned m0   = (unsigned)chunk * 4u;
        const unsigned base = m0 * (unsigned)F_IN;   // fits 32 bits (<143.3M)

        unsigned long long acc[32];                  // a = row*8 + pcol
#pragma unroll
        for (int a = 0; a < 32; a++) acc[a] = 0ull;

        float Axa[4], Axb[4];   // buffer A
        float Bxa[4], Bxb[4];   // buffer B
        float Cxa[4], Cxb[4];   // buffer C

        // compute one 64-k block from (xa, xb) with W at k0
#define COMPUTE_BLOCK(k0v, xa, xb)                                            \
        {                                                                     \
            const int kA = (k0v) + lane;                                      \
            unsigned long long xx[4];                                         \
            _Pragma("unroll")                                                 \
            for (int i = 0; i < 4; i++) xx[i] = splat2(xa[i]);                \
            _Pragma("unroll")                                                 \
            for (int p = 0; p < 8; p++) {                                     \
                unsigned long long w = sWp[p * KPAD + kA];                    \
                _Pragma("unroll")                                             \
                for (int i = 0; i < 4; i++)                                   \
                    acc[i * 8 + p] = fma2(xx[i], w, acc[i * 8 + p]);          \
            }                                                                 \
            const int kB = (k0v) + 32 + lane;                                 \
            _Pragma("unroll")                                                 \
            for (int i = 0; i < 4; i++) xx[i] = splat2(xb[i]);                \
            _Pragma("unroll")                                                 \
            for (int p = 0; p < 8; p++) {                                     \
                unsigned long long w = sWp[p * KPAD + kB];                    \
                _Pragma("unroll")                                             \
                for (int i = 0; i < 4; i++)                                   \
                    acc[i * 8 + p] = fma2(xx[i], w, acc[i * 8 + p]);          \
            }                                                                 \
        }

        // prefetch a 64-k block (clamped columns) into (xa, xb)
#define PREFETCH_BLOCK(k0v, xa, xb)                                           \
        {                                                                     \
            const unsigned ka = (unsigned)min((k0v) + lane,      F_IN - 1);   \
            const unsigned kb = (unsigned)min((k0v) + 32 + lane, F_IN - 1);   \
            _Pragma("unroll")                                                 \
            for (int i = 0; i < 4; i++) {                                     \
                xa[i] = ldcs(X + base + (unsigned)i * F_IN + ka);             \
                xb[i] = ldcs(X + base + (unsigned)i * F_IN + kb);             \
            }                                                                 \
        }

        // preload blocks 0,1 -> A,B (block 0/1 columns always valid)
        PREFETCH_BLOCK(0,  Axa, Axb);
        PREFETCH_BLOCK(64, Bxa, Bxb);

        // 24 blocks in 8 triples; prefetch distance = 2 blocks. Trailing
        // prefetches past KPAD are clamped and never used.
#pragma unroll 1
        for (int t = 0; t < 8; t++) {
            const int kb0 = t * 192;
            PREFETCH_BLOCK(kb0 + 128, Cxa, Cxb);
            COMPUTE_BLOCK (kb0,       Axa, Axb);
            PREFETCH_BLOCK(kb0 + 192, Axa, Axb);
            COMPUTE_BLOCK (kb0 + 64,  Bxa, Bxb);
            PREFETCH_BLOCK(kb0 + 256, Bxa, Bxb);
            COMPUTE_BLOCK (kb0 + 128, Cxa, Cxb);
        }
#undef COMPUTE_BLOCK
#undef PREFETCH_BLOCK

        // transpose-reduce: after 5 steps lane l holds the full sum of
        // original acc slot a = l  (row = l>>3, pcol = l&7). 31 shfl total.
        {
            int n = 32;
#pragma unroll
            for (int m = 16; m > 0; m >>= 1) {
                n >>= 1;
#pragma unroll
                for (int j = 0; j < 16; j++) {
                    if (j >= n) break;
                    unsigned long long mine = (lane & m) ? acc[j]     : acc[j + n];
                    unsigned long long keep = (lane & m) ? acc[j + n] : acc[j];
                    unsigned long long recv = __shfl_xor_sync(0xffffffffu, mine, m);
                    acc[j] = add2(keep, recv);
                }
            }
        }

        // coalesced store: lane l -> row (l>>3), float-pair (l&7)
        {
            const int i = lane >> 3, p = lane & 7;
            float s = g_ns[m0 + i];
            float2 v = unpack2(acc[0]);
            float2* o = (float2*)(g_h1 + (size_t)(m0 + i) * F_HID);
            o[p] = make_float2(v.x * s, v.y * s);
        }
    }
}

// ---------------- scatter 1: agg1[dst] += h1[src]  (16 wide) ----------------
__global__ void scatter1_kernel(const int* __restrict__ src,
                                const int* __restrict__ dst) {
    int e = blockIdx.x * blockDim.x + threadIdx.x;
    if (e >= N_EDGES) return;
    int s = src[e], d = dst[e];
    const float4* hs = (const float4*)(g_h1 + (size_t)s * F_HID);
    float4 a = hs[0], b = hs[1], c = hs[2], f = hs[3];
    float* base = g_agg1 + (size_t)d * F_HID;
    red_add_v4(base + 0,  a);
    red_add_v4(base + 4,  b);
    red_add_v4(base + 8,  c);
    red_add_v4(base + 12, f);
}

// ---------------- GEMM2: h2 = diag(ns) * relu(agg1*nd + b1) @ W2 ------------
__global__ void gemm2_kernel(const float* __restrict__ b1,
                             const float* __restrict__ W2) {
    __shared__ float sW[F_HID * F_OUT];
    __shared__ float sb[F_HID];
    if (threadIdx.x < F_HID * F_OUT) sW[threadIdx.x] = W2[threadIdx.x];
    if (threadIdx.x < F_HID)         sb[threadIdx.x] = b1[threadIdx.x];
    __syncthreads();

    int n = blockIdx.x * blockDim.x + threadIdx.x;
    if (n >= N_NODES) return;

    float ndv = g_nd[n], nsv = g_ns[n];
    const float4* a4 = (const float4*)(g_agg1 + (size_t)n * F_HID);
    float x[F_HID];
#pragma unroll
    for (int q = 0; q < 4; q++) {
        float4 v = a4[q];
        x[q*4+0] = v.x; x[q*4+1] = v.y; x[q*4+2] = v.z; x[q*4+3] = v.w;
    }
    float o[F_OUT];
#pragma unroll
    for (int j = 0; j < F_OUT; j++) o[j] = 0.f;
#pragma unroll
    for (int i = 0; i < F_HID; i++) {
        float xi = fmaxf(fmaf(x[i], ndv, sb[i]), 0.f) * nsv;
#pragma unroll
        for (int j = 0; j < F_OUT; j++) o[j] = fmaf(xi, sW[i * F_OUT + j], o[j]);
    }
    float4* hp = (float4*)(g_h2 + (size_t)n * 8);
    hp[0] = make_float4(o[0], o[1], o[2], o[3]);
    hp[1] = make_float4(o[4], o[5], o[6], 0.f);   // pad lane stays 0
}

// ---------------- scatter 2: agg2[dst] += h2[src]  (8 wide, padded) ---------
__global__ void scatter2_kernel(const int* __restrict__ src,
                                const int* __restrict__ dst) {
    int e = blockIdx.x * blockDim.x + threadIdx.x;
    if (e >= N_EDGES) return;
    int s = src[e], d = dst[e];
    const float4* hs = (const float4*)(g_h2 + (size_t)s * 8);
    float4 a = hs[0], b = hs[1];
    float* base = g_agg2 + (size_t)d * 8;
    red_add_v4(base + 0, a);
    red_add_v4(base + 4, b);
}

// ---------------- finalize: out = agg2*nd + b2 -------------------------------
__global__ void final_kernel(const float* __restrict__ b2,
                             float* __restrict__ out) {
    int t = blockIdx.x * blockDim.x + threadIdx.x;
    if (t >= N_NODES * F_OUT) return;
    int n = t / F_OUT;
    int j = t - n * F_OUT;
    out[t] = fmaf(g_agg2[(size_t)n * 8 + j], g_nd[n], b2[j]);
}

// ---------------- launch ------------------------------------------------------
extern "C" void kernel_launch(void* const* d_in, const int* in_sizes, int n_in,
                              void* d_out, int out_size) {
    const float* X   = (const float*)d_in[0];
    const int*   src = (const int*)  d_in[1];
    const int*   dst = (const int*)  d_in[2];
    const float* W1  = (const float*)d_in[3];
    const float* b1  = (const float*)d_in[4];
    const float* W2  = (const float*)d_in[5];
    const float* b2  = (const float*)d_in[6];
    float* out = (float*)d_out;

    const int g1_smem = 8 * KPAD * 8;   // 98304 bytes
    static int attr_done = 0;
    if (!attr_done) {   // idempotent host-side attribute, not a capture op
        cudaFuncSetAttribute(gemm1_kernel,
                             cudaFuncAttributeMaxDynamicSharedMemorySize, g1_smem);
        attr_done = 1;
    }

    zero_kernel  <<<(N_NODES * F_HID / 4 + 255) / 256, 256>>>();
    degree_kernel<<<N_EDGES / 256, 256>>>(src, dst);
    norm_kernel  <<<(N_NODES + 255) / 256, 256>>>();
    gemm1_kernel <<<G1_GRID, 256, g1_smem>>>(X, W1);
    scatter1_kernel<<<N_EDGES / 256, 256>>>(src, dst);
    gemm2_kernel <<<(N_NODES + 255) / 256, 256>>>(b1, W2);
    scatter2_kernel<<<N_EDGES / 256, 256>>>(src, dst);
    final_kernel <<<(N_NODES * F_OUT + 255) / 256, 256>>>(b2, out);
}

// round 7
// speedup vs baseline: 1.5547x; 1.1202x over previous
#include <cuda_runtime.h>
#include <cstdint>

#define N_NODES 100000
#define N_EDGES 3200000
#define F_IN    1433
#define F_HID   16
#define F_OUT   7

#define KPAD     1536            // F_IN padded to multiple of 128 (zero-filled W)
#define G1_GRID  296             // 148 SMs x 2 blocks
#define NCHUNK   (N_NODES / 4)   // 25000 4-row warp chunks

// ---------------- scratch (device globals; no allocation allowed) ----------
__device__ float g_h1  [N_NODES * F_HID];   // ns-scaled X @ W1
__device__ float g_agg1[N_NODES * F_HID];   // gather-aggregated layer 1
__device__ float g_h2  [N_NODES * 8];       // padded to 8
__device__ float g_agg2[N_NODES * 8];
__device__ float g_degout[N_NODES];
__device__ int   g_degin [N_NODES];         // int in-degree (CSR)
__device__ float g_ns[N_NODES];
__device__ float g_nd[N_NODES];
__device__ int   g_off   [N_NODES];         // CSR range start per dst
__device__ int   g_cursor[N_NODES];
__device__ int   g_csr_src[N_EDGES];
__device__ int   g_total;

// ---- packed f32x2 helpers (sm_103a FFMA2 — PTX-only form) ------------------
__device__ __forceinline__ unsigned long long fma2(unsigned long long a,
                                                   unsigned long long b,
                                                   unsigned long long c) {
    unsigned long long d;
    asm("fma.rn.f32x2 %0, %1, %2, %3;" : "=l"(d) : "l"(a), "l"(b), "l"(c));
    return d;
}
__device__ __forceinline__ unsigned long long add2(unsigned long long a,
                                                   unsigned long long b) {
    unsigned long long d;
    asm("add.rn.f32x2 %0, %1, %2;" : "=l"(d) : "l"(a), "l"(b));
    return d;
}
__device__ __forceinline__ unsigned long long splat2(float x) {
    unsigned long long d;
    asm("mov.b64 %0, {%1, %1};" : "=l"(d) : "f"(x));
    return d;
}
__device__ __forceinline__ float2 unpack2(unsigned long long v) {
    float2 r;
    asm("mov.b64 {%0, %1}, %2;" : "=f"(r.x), "=f"(r.y) : "l"(v));
    return r;
}
__device__ __forceinline__ float ldcs(const float* p) {
    float v;
    asm("ld.global.cs.f32 %0, [%1];" : "=f"(v) : "l"(p));
    return v;
}

// ---------------- zeroing (graph-replay safe; no agg zeroing needed) --------
__global__ void zero_kernel() {
    int t = blockIdx.x * blockDim.x + threadIdx.x;
    if (t < N_NODES) { g_degout[t] = 0.f; g_degin[t] = 0; g_cursor[t] = 0; }
    if (t == 0) g_total = 0;
}

// ---------------- degrees ----------------------------------------------------
__global__ void degree_kernel(const int* __restrict__ src,
                              const int* __restrict__ dst) {
    int e = blockIdx.x * blockDim.x + threadIdx.x;
    if (e >= N_EDGES) return;
    atomicAdd(&g_degout[src[e]], 1.0f);
    atomicAdd(&g_degin [dst[e]], 1);
}

// ---------------- norms + CSR offsets (warp-aggregated range assignment) ----
// Ranges are handed out warp-by-warp in arbitrary order (atomic on g_total)
// but each node gets a unique contiguous [off, off+deg) slice — a valid CSR.
// N_NODES % 32 == 0, so active warps are always full.
__global__ void norm_offset_kernel() {
    int n = blockIdx.x * blockDim.x + threadIdx.x;
    if (n >= N_NODES) return;
    int lane = threadIdx.x & 31;
    int d = g_degin[n];

    int incl = d;
#pragma unroll
    for (int o = 1; o < 32; o <<= 1) {
        int v = __shfl_up_sync(0xffffffffu, incl, o);
        if (lane >= o) incl += v;
    }
    int base = 0;
    if (lane == 31) base = atomicAdd(&g_total, incl);
    base = __shfl_sync(0xffffffffu, base, 31);

    g_off[n] = base + incl - d;
    g_ns[n] = rsqrtf(fmaxf(g_degout[n], 1.0f));
    g_nd[n] = rsqrtf(fmaxf((float)d, 1.0f));
}

// ---------------- CSR edge placement ----------------------------------------
__global__ void place_kernel(const int* __restrict__ src,
                             const int* __restrict__ dst) {
    int e = blockIdx.x * blockDim.x + threadIdx.x;
    if (e >= N_EDGES) return;
    int d = dst[e];
    int p = atomicAdd(&g_cursor[d], 1);
    g_csr_src[g_off[d] + p] = src[e];
}

// ---------------- GEMM1: h1 = diag(ns) * X @ W1  (unchanged from R6) --------
__global__ __launch_bounds__(256, 2) void gemm1_kernel(const float* __restrict__ X,
                                                       const float* __restrict__ W) {
    extern __shared__ unsigned long long sWp[];   // [8][KPAD] packed float2

    const float2* Wv = (const float2*)W;          // Wv[k*8 + p]
    for (int idx = threadIdx.x; idx < 8 * KPAD; idx += 256) {
        int k = idx >> 3, p = idx & 7;
        float2 v = (k < F_IN) ? Wv[k * 8 + p] : make_float2(0.f, 0.f);
        unsigned long long pk;
        asm("mov.b64 %0, {%1, %2};" : "=l"(pk) : "f"(v.x), "f"(v.y));
        sWp[p * KPAD + k] = pk;
    }
    __syncthreads();

    const int lane = threadIdx.x & 31;
    const int gw   = blockIdx.x * 8 + (threadIdx.x >> 5);

    for (int chunk = gw; chunk < NCHUNK; chunk += G1_GRID * 8) {
        const unsigned m0   = (unsigned)chunk * 4u;
        const unsigned base = m0 * (unsigned)F_IN;

        unsigned long long acc[32];
#pragma unroll
        for (int a = 0; a < 32; a++) acc[a] = 0ull;

        float Axa[4], Axb[4];
        float Bxa[4], Bxb[4];
        float Cxa[4], Cxb[4];

#define COMPUTE_BLOCK(k0v, xa, xb)                                            \
        {                                                                     \
            const int kA = (k0v) + lane;                                      \
            unsigned long long xx[4];                                         \
            _Pragma("unroll")                                                 \
            for (int i = 0; i < 4; i++) xx[i] = splat2(xa[i]);                \
            _Pragma("unroll")                                                 \
            for (int p = 0; p < 8; p++) {                                     \
                unsigned long long w = sWp[p * KPAD + kA];                    \
                _Pragma("unroll")                                             \
                for (int i = 0; i < 4; i++)                                   \
                    acc[i * 8 + p] = fma2(xx[i], w, acc[i * 8 + p]);          \
            }                                                                 \
            const int kB = (k0v) + 32 + lane;                                 \
            _Pragma("unroll")                                                 \
            for (int i = 0; i < 4; i++) xx[i] = splat2(xb[i]);                \
            _Pragma("unroll")                                                 \
            for (int p = 0; p < 8; p++) {                                     \
                unsigned long long w = sWp[p * KPAD + kB];                    \
                _Pragma("unroll")                                             \
                for (int i = 0; i < 4; i++)                                   \
                    acc[i * 8 + p] = fma2(xx[i], w, acc[i * 8 + p]);          \
            }                                                                 \
        }

#define PREFETCH_BLOCK(k0v, xa, xb)                                           \
        {                                                                     \
            const unsigned ka = (unsigned)min((k0v) + lane,      F_IN - 1);   \
            const unsigned kb = (unsigned)min((k0v) + 32 + lane, F_IN - 1);   \
            _Pragma("unroll")                                                 \
            for (int i = 0; i < 4; i++) {                                     \
                xa[i] = ldcs(X + base + (unsigned)i * F_IN + ka);             \
                xb[i] = ldcs(X + base + (unsigned)i * F_IN + kb);             \
            }                                                                 \
        }

        PREFETCH_BLOCK(0,  Axa, Axb);
        PREFETCH_BLOCK(64, Bxa, Bxb);

#pragma unroll 1
        for (int t = 0; t < 8; t++) {
            const int kb0 = t * 192;
            PREFETCH_BLOCK(kb0 + 128, Cxa, Cxb);
            COMPUTE_BLOCK (kb0,       Axa, Axb);
            PREFETCH_BLOCK(kb0 + 192, Axa, Axb);
            COMPUTE_BLOCK (kb0 + 64,  Bxa, Bxb);
            PREFETCH_BLOCK(kb0 + 256, Bxa, Bxb);
            COMPUTE_BLOCK (kb0 + 128, Cxa, Cxb);
        }
#undef COMPUTE_BLOCK
#undef PREFETCH_BLOCK

        // transpose-reduce: lane l ends with acc slot (row = l>>3, pcol = l&7)
        {
            int n = 32;
#pragma unroll
            for (int m = 16; m > 0; m >>= 1) {
                n >>= 1;
#pragma unroll
                for (int j = 0; j < 16; j++) {
                    if (j >= n) break;
                    unsigned long long mine = (lane & m) ? acc[j]     : acc[j + n];
                    unsigned long long keep = (lane & m) ? acc[j + n] : acc[j];
                    unsigned long long recv = __shfl_xor_sync(0xffffffffu, mine, m);
                    acc[j] = add2(keep, recv);
                }
            }
        }
        {
            const int i = lane >> 3, p = lane & 7;
            float s = g_ns[m0 + i];
            float2 v = unpack2(acc[0]);
            float2* o = (float2*)(g_h1 + (size_t)(m0 + i) * F_HID);
            o[p] = make_float2(v.x * s, v.y * s);
        }
    }
}

// ---------------- agg1: agg1[n] = sum_{e in CSR[n]} h1[src(e)]  (16 wide) ---
// One warp per dst node; 4 lanes per edge (each lane one float4 slot),
// 8 edges in flight. Pure gathers (L2-hit) + register accumulation; no atomics.
__global__ __launch_bounds__(256) void agg1_kernel() {
    int gw   = blockIdx.x * 8 + (threadIdx.x >> 5);   // node id (grid exact)
    int lane = threadIdx.x & 31;
    int q  = lane & 3;
    int es = lane >> 2;

    int o  = g_off[gw];
    int nE = g_degin[gw];

    float4 acc = make_float4(0.f, 0.f, 0.f, 0.f);
    const float4* h1v = (const float4*)g_h1;
    for (int i = es; i < nE; i += 8) {
        int s = __ldg(&g_csr_src[o + i]);
        float4 v = h1v[(size_t)s * 4 + q];
        acc.x += v.x; acc.y += v.y; acc.z += v.z; acc.w += v.w;
    }
#pragma unroll
    for (int m = 4; m <= 16; m <<= 1) {
        acc.x += __shfl_xor_sync(0xffffffffu, acc.x, m);
        acc.y += __shfl_xor_sync(0xffffffffu, acc.y, m);
        acc.z += __shfl_xor_sync(0xffffffffu, acc.z, m);
        acc.w += __shfl_xor_sync(0xffffffffu, acc.w, m);
    }
    if (lane < 4) ((float4*)g_agg1)[(size_t)gw * 4 + lane] = acc;
}

// ---------------- GEMM2: h2 = diag(ns) * relu(agg1*nd + b1) @ W2 ------------
__global__ void gemm2_kernel(const float* __restrict__ b1,
                             const float* __restrict__ W2) {
    __shared__ float sW[F_HID * F_OUT];
    __shared__ float sb[F_HID];
    if (threadIdx.x < F_HID * F_OUT) sW[threadIdx.x] = W2[threadIdx.x];
    if (threadIdx.x < F_HID)         sb[threadIdx.x] = b1[threadIdx.x];
    __syncthreads();

    int n = blockIdx.x * blockDim.x + threadIdx.x;
    if (n >= N_NODES) return;

    float ndv = g_nd[n], nsv = g_ns[n];
    const float4* a4 = (const float4*)(g_agg1 + (size_t)n * F_HID);
    float x[F_HID];
#pragma unroll
    for (int q = 0; q < 4; q++) {
        float4 v = a4[q];
        x[q*4+0] = v.x; x[q*4+1] = v.y; x[q*4+2] = v.z; x[q*4+3] = v.w;
    }
    float o[F_OUT];
#pragma unroll
    for (int j = 0; j < F_OUT; j++) o[j] = 0.f;
#pragma unroll
    for (int i = 0; i < F_HID; i++) {
        float xi = fmaxf(fmaf(x[i], ndv, sb[i]), 0.f) * nsv;
#pragma unroll
        for (int j = 0; j < F_OUT; j++) o[j] = fmaf(xi, sW[i * F_OUT + j], o[j]);
    }
    float4* hp = (float4*)(g_h2 + (size_t)n * 8);
    hp[0] = make_float4(o[0], o[1], o[2], o[3]);
    hp[1] = make_float4(o[4], o[5], o[6], 0.f);   // pad lane stays 0
}

// ---------------- agg2: agg2[n] = sum h2[src]  (8 wide, 2 lanes/edge) -------
__global__ __launch_bounds__(256) void agg2_kernel() {
    int gw   = blockIdx.x * 8 + (threadIdx.x >> 5);
    int lane = threadIdx.x & 31;
    int q  = lane & 1;
    int es = lane >> 1;

    int o  = g_off[gw];
    int nE = g_degin[gw];

    float4 acc = make_float4(0.f, 0.f, 0.f, 0.f);
    const float4* h2v = (const float4*)g_h2;
    for (int i = es; i < nE; i += 16) {
        int s = __ldg(&g_csr_src[o + i]);
        float4 v = h2v[(size_t)s * 2 + q];
        acc.x += v.x; acc.y += v.y; acc.z += v.z; acc.w += v.w;
    }
#pragma unroll
    for (int m = 2; m <= 16; m <<= 1) {
        acc.x += __shfl_xor_sync(0xffffffffu, acc.x, m);
        acc.y += __shfl_xor_sync(0xffffffffu, acc.y, m);
        acc.z += __shfl_xor_sync(0xffffffffu, acc.z, m);
        acc.w += __shfl_xor_sync(0xffffffffu, acc.w, m);
    }
    if (lane < 2) ((float4*)g_agg2)[(size_t)gw * 2 + lane] = acc;
}

// ---------------- finalize: out = agg2*nd + b2 -------------------------------
__global__ void final_kernel(const float* __restrict__ b2,
                             float* __restrict__ out) {
    int t = blockIdx.x * blockDim.x + threadIdx.x;
    if (t >= N_NODES * F_OUT) return;
    int n = t / F_OUT;
    int j = t - n * F_OUT;
    out[t] = fmaf(g_agg2[(size_t)n * 8 + j], g_nd[n], b2[j]);
}

// ---------------- launch ------------------------------------------------------
extern "C" void kernel_launch(void* const* d_in, const int* in_sizes, int n_in,
                              void* d_out, int out_size) {
    const float* X   = (const float*)d_in[0];
    const int*   src = (const int*)  d_in[1];
    const int*   dst = (const int*)  d_in[2];
    const float* W1  = (const float*)d_in[3];
    const float* b1  = (const float*)d_in[4];
    const float* W2  = (const float*)d_in[5];
    const float* b2  = (const float*)d_in[6];
    float* out = (float*)d_out;

    const int g1_smem = 8 * KPAD * 8;   // 98304 bytes
    static int attr_done = 0;
    if (!attr_done) {   // idempotent host-side attribute, not a capture op
        cudaFuncSetAttribute(gemm1_kernel,
                             cudaFuncAttributeMaxDynamicSharedMemorySize, g1_smem);
        attr_done = 1;
    }

    zero_kernel       <<<(N_NODES + 255) / 256, 256>>>();
    degree_kernel     <<<N_EDGES / 256, 256>>>(src, dst);
    norm_offset_kernel<<<(N_NODES + 255) / 256, 256>>>();
    place_kernel      <<<N_EDGES / 256, 256>>>(src, dst);
    gemm1_kernel      <<<G1_GRID, 256, g1_smem>>>(X, W1);
    agg1_kernel       <<<N_NODES / 8, 256>>>();
    gemm2_kernel      <<<(N_NODES + 255) / 256, 256>>>(b1, W2);
    agg2_kernel       <<<N_NODES / 8, 256>>>();
    final_kernel      <<<(N_NODES * F_OUT + 255) / 256, 256>>>(b2, out);
}

// round 8
// speedup vs baseline: 1.5707x; 1.0103x over previous
#include <cuda_runtime.h>
#include <cstdint>

#define N_NODES 100000
#define N_EDGES 3200000
#define F_IN    1433
#define F_HID   16
#define F_OUT   7

#define KPAD     1536            // F_IN padded to multiple of 128 (zero-filled W)
#define G1_GRID  296             // 148 SMs x 2 blocks
#define NCHUNK   (N_NODES / 4)   // 25000 4-row warp chunks

// ---------------- scratch (device globals; no allocation allowed) ----------
__device__ float g_h1  [N_NODES * F_HID];   // ns-scaled X @ W1
__device__ float g_agg1[N_NODES * F_HID];   // gather-aggregated layer 1
__device__ float g_h2  [N_NODES * 8];       // padded to 8
__device__ float g_degout[N_NODES];
__device__ int   g_degin [N_NODES];         // int in-degree (CSR)
__device__ float g_ns[N_NODES];
__device__ float g_nd[N_NODES];
__device__ int   g_off   [N_NODES];         // CSR range start per dst
__device__ int   g_cursor[N_NODES];         // initialized to g_off
__device__ int   g_csr_src[N_EDGES];
__device__ int   g_total;

// ---- packed f32x2 helpers (sm_103a FFMA2 — PTX-only form) ------------------
__device__ __forceinline__ unsigned long long fma2(unsigned long long a,
                                                   unsigned long long b,
                                                   unsigned long long c) {
    unsigned long long d;
    asm("fma.rn.f32x2 %0, %1, %2, %3;" : "=l"(d) : "l"(a), "l"(b), "l"(c));
    return d;
}
__device__ __forceinline__ unsigned long long add2(unsigned long long a,
                                                   unsigned long long b) {
    unsigned long long d;
    asm("add.rn.f32x2 %0, %1, %2;" : "=l"(d) : "l"(a), "l"(b));
    return d;
}
__device__ __forceinline__ unsigned long long splat2(float x) {
    unsigned long long d;
    asm("mov.b64 %0, {%1, %1};" : "=l"(d) : "f"(x));
    return d;
}
__device__ __forceinline__ float2 unpack2(unsigned long long v) {
    float2 r;
    asm("mov.b64 {%0, %1}, %2;" : "=f"(r.x), "=f"(r.y) : "l"(v));
    return r;
}
__device__ __forceinline__ float ldcs(const float* p) {
    float v;
    asm("ld.global.cs.f32 %0, [%1];" : "=f"(v) : "l"(p));
    return v;
}

// ---------------- zeroing (graph-replay safe) --------------------------------
__global__ void zero_kernel() {
    int t = blockIdx.x * blockDim.x + threadIdx.x;
    if (t < N_NODES) { g_degout[t] = 0.f; g_degin[t] = 0; }
    if (t == 0) g_total = 0;
}

// ---------------- degrees ----------------------------------------------------
__global__ void degree_kernel(const int* __restrict__ src,
                              const int* __restrict__ dst) {
    int e = blockIdx.x * blockDim.x + threadIdx.x;
    if (e >= N_EDGES) return;
    atomicAdd(&g_degout[src[e]], 1.0f);
    atomicAdd(&g_degin [dst[e]], 1);
}

// ---------------- norms + CSR offsets (warp-aggregated range assignment) ----
// Ranges are handed out warp-by-warp in arbitrary order (atomic on g_total)
// but each node gets a unique contiguous [off, off+deg) slice — a valid CSR.
// Cursor is initialized to off so place_kernel needs no g_off read.
__global__ void norm_offset_kernel() {
    int n = blockIdx.x * blockDim.x + threadIdx.x;
    if (n >= N_NODES) return;
    int lane = threadIdx.x & 31;
    int d = g_degin[n];

    int incl = d;
#pragma unroll
    for (int o = 1; o < 32; o <<= 1) {
        int v = __shfl_up_sync(0xffffffffu, incl, o);
        if (lane >= o) incl += v;
    }
    int base = 0;
    if (lane == 31) base = atomicAdd(&g_total, incl);
    base = __shfl_sync(0xffffffffu, base, 31);

    int off = base + incl - d;
    g_off[n]    = off;
    g_cursor[n] = off;
    g_ns[n] = rsqrtf(fmaxf(g_degout[n], 1.0f));
    g_nd[n] = rsqrtf(fmaxf((float)d, 1.0f));
}

// ---------------- CSR edge placement (cursor pre-biased by offset) ----------
__global__ void place_kernel(const int* __restrict__ src,
                             const int* __restrict__ dst) {
    int e = blockIdx.x * blockDim.x + threadIdx.x;
    if (e >= N_EDGES) return;
    int p = atomicAdd(&g_cursor[dst[e]], 1);
    g_csr_src[p] = src[e];
}

// ---------------- GEMM1: h1 = diag(ns) * X @ W1  (unchanged) ----------------
__global__ __launch_bounds__(256, 2) void gemm1_kernel(const float* __restrict__ X,
                                                       const float* __restrict__ W) {
    extern __shared__ unsigned long long sWp[];   // [8][KPAD] packed float2

    const float2* Wv = (const float2*)W;          // Wv[k*8 + p]
    for (int idx = threadIdx.x; idx < 8 * KPAD; idx += 256) {
        int k = idx >> 3, p = idx & 7;
        float2 v = (k < F_IN) ? Wv[k * 8 + p] : make_float2(0.f, 0.f);
        unsigned long long pk;
        asm("mov.b64 %0, {%1, %2};" : "=l"(pk) : "f"(v.x), "f"(v.y));
        sWp[p * KPAD + k] = pk;
    }
    __syncthreads();

    const int lane = threadIdx.x & 31;
    const int gw   = blockIdx.x * 8 + (threadIdx.x >> 5);

    for (int chunk = gw; chunk < NCHUNK; chunk += G1_GRID * 8) {
        const unsigned m0   = (unsigned)chunk * 4u;
        const unsigned base = m0 * (unsigned)F_IN;

        unsigned long long acc[32];
#pragma unroll
        for (int a = 0; a < 32; a++) acc[a] = 0ull;

        float Axa[4], Axb[4];
        float Bxa[4], Bxb[4];
        float Cxa[4], Cxb[4];

#define COMPUTE_BLOCK(k0v, xa, xb)                                            \
        {                                                                     \
            const int kA = (k0v) + lane;                                      \
            unsigned long long xx[4];                                         \
            _Pragma("unroll")                                                 \
            for (int i = 0; i < 4; i++) xx[i] = splat2(xa[i]);                \
            _Pragma("unroll")                                                 \
            for (int p = 0; p < 8; p++) {                                     \
                unsigned long long w = sWp[p * KPAD + kA];                    \
                _Pragma("unroll")                                             \
                for (int i = 0; i < 4; i++)                                   \
                    acc[i * 8 + p] = fma2(xx[i], w, acc[i * 8 + p]);          \
            }                                                                 \
            const int kB = (k0v) + 32 + lane;                                 \
            _Pragma("unroll")                                                 \
            for (int i = 0; i < 4; i++) xx[i] = splat2(xb[i]);                \
            _Pragma("unroll")                                                 \
            for (int p = 0; p < 8; p++) {                                     \
                unsigned long long w = sWp[p * KPAD + kB];                    \
                _Pragma("unroll")                                             \
                for (int i = 0; i < 4; i++)                                   \
                    acc[i * 8 + p] = fma2(xx[i], w, acc[i * 8 + p]);          \
            }                                                                 \
        }

#define PREFETCH_BLOCK(k0v, xa, xb)                                           \
        {                                                                     \
            const unsigned ka = (unsigned)min((k0v) + lane,      F_IN - 1);   \
            const unsigned kb = (unsigned)min((k0v) + 32 + lane, F_IN - 1);   \
            _Pragma("unroll")                                                 \
            for (int i = 0; i < 4; i++) {                                     \
                xa[i] = ldcs(X + base + (unsigned)i * F_IN + ka);             \
                xb[i] = ldcs(X + base + (unsigned)i * F_IN + kb);             \
            }                                                                 \
        }

        PREFETCH_BLOCK(0,  Axa, Axb);
        PREFETCH_BLOCK(64, Bxa, Bxb);

#pragma unroll 1
        for (int t = 0; t < 8; t++) {
            const int kb0 = t * 192;
            PREFETCH_BLOCK(kb0 + 128, Cxa, Cxb);
            COMPUTE_BLOCK (kb0,       Axa, Axb);
            PREFETCH_BLOCK(kb0 + 192, Axa, Axb);
            COMPUTE_BLOCK (kb0 + 64,  Bxa, Bxb);
            PREFETCH_BLOCK(kb0 + 256, Bxa, Bxb);
            COMPUTE_BLOCK (kb0 + 128, Cxa, Cxb);
        }
#undef COMPUTE_BLOCK
#undef PREFETCH_BLOCK

        // transpose-reduce: lane l ends with acc slot (row = l>>3, pcol = l&7)
        {
            int n = 32;
#pragma unroll
            for (int m = 16; m > 0; m >>= 1) {
                n >>= 1;
#pragma unroll
                for (int j = 0; j < 16; j++) {
                    if (j >= n) break;
                    unsigned long long mine = (lane & m) ? acc[j]     : acc[j + n];
                    unsigned long long keep = (lane & m) ? acc[j + n] : acc[j];
                    unsigned long long recv = __shfl_xor_sync(0xffffffffu, mine, m);
                    acc[j] = add2(keep, recv);
                }
            }
        }
        {
            const int i = lane >> 3, p = lane & 7;
            float s = g_ns[m0 + i];
            float2 v = unpack2(acc[0]);
            float2* o = (float2*)(g_h1 + (size_t)(m0 + i) * F_HID);
            o[p] = make_float2(v.x * s, v.y * s);
        }
    }
}

// ---------------- agg1: agg1[n] = sum_{e in CSR[n]} h1[src(e)]  (16 wide) ---
__global__ __launch_bounds__(256) void agg1_kernel() {
    int gw   = blockIdx.x * 8 + (threadIdx.x >> 5);   // node id (grid exact)
    int lane = threadIdx.x & 31;
    int q  = lane & 3;
    int es = lane >> 2;

    int o  = g_off[gw];
    int nE = g_degin[gw];

    float4 acc = make_float4(0.f, 0.f, 0.f, 0.f);
    const float4* h1v = (const float4*)g_h1;
    for (int i = es; i < nE; i += 8) {
        int s = __ldg(&g_csr_src[o + i]);
        float4 v = h1v[(size_t)s * 4 + q];
        acc.x += v.x; acc.y += v.y; acc.z += v.z; acc.w += v.w;
    }
#pragma unroll
    for (int m = 4; m <= 16; m <<= 1) {
        acc.x += __shfl_xor_sync(0xffffffffu, acc.x, m);
        acc.y += __shfl_xor_sync(0xffffffffu, acc.y, m);
        acc.z += __shfl_xor_sync(0xffffffffu, acc.z, m);
        acc.w += __shfl_xor_sync(0xffffffffu, acc.w, m);
    }
    if (lane < 4) ((float4*)g_agg1)[(size_t)gw * 4 + lane] = acc;
}

// ---------------- GEMM2: h2 = diag(ns) * relu(agg1*nd + b1) @ W2 ------------
__global__ void gemm2_kernel(const float* __restrict__ b1,
                             const float* __restrict__ W2) {
    __shared__ float sW[F_HID * F_OUT];
    __shared__ float sb[F_HID];
    if (threadIdx.x < F_HID * F_OUT) sW[threadIdx.x] = W2[threadIdx.x];
    if (threadIdx.x < F_HID)         sb[threadIdx.x] = b1[threadIdx.x];
    __syncthreads();

    int n = blockIdx.x * blockDim.x + threadIdx.x;
    if (n >= N_NODES) return;

    float ndv = g_nd[n], nsv = g_ns[n];
    const float4* a4 = (const float4*)(g_agg1 + (size_t)n * F_HID);
    float x[F_HID];
#pragma unroll
    for (int q = 0; q < 4; q++) {
        float4 v = a4[q];
        x[q*4+0] = v.x; x[q*4+1] = v.y; x[q*4+2] = v.z; x[q*4+3] = v.w;
    }
    float o[F_OUT];
#pragma unroll
    for (int j = 0; j < F_OUT; j++) o[j] = 0.f;
#pragma unroll
    for (int i = 0; i < F_HID; i++) {
        float xi = fmaxf(fmaf(x[i], ndv, sb[i]), 0.f) * nsv;
#pragma unroll
        for (int j = 0; j < F_OUT; j++) o[j] = fmaf(xi, sW[i * F_OUT + j], o[j]);
    }
    float4* hp = (float4*)(g_h2 + (size_t)n * 8);
    hp[0] = make_float4(o[0], o[1], o[2], o[3]);
    hp[1] = make_float4(o[4], o[5], o[6], 0.f);   // pad lane stays 0
}

// ---------------- agg2 + finalize: out[n] = (sum h2[src]) * nd + b2 ----------
__global__ __launch_bounds__(256) void agg2_final_kernel(const float* __restrict__ b2,
                                                         float* __restrict__ out) {
    int gw   = blockIdx.x * 8 + (threadIdx.x >> 5);
    int lane = threadIdx.x & 31;
    int q  = lane & 1;
    int es = lane >> 1;

    int o  = g_off[gw];
    int nE = g_degin[gw];

    float4 acc = make_float4(0.f, 0.f, 0.f, 0.f);
    const float4* h2v = (const float4*)g_h2;
    for (int i = es; i < nE; i += 16) {
        int s = __ldg(&g_csr_src[o + i]);
        float4 v = h2v[(size_t)s * 2 + q];
        acc.x += v.x; acc.y += v.y; acc.z += v.z; acc.w += v.w;
    }
#pragma unroll
    for (int m = 2; m <= 16; m <<= 1) {
        acc.x += __shfl_xor_sync(0xffffffffu, acc.x, m);
        acc.y += __shfl_xor_sync(0xffffffffu, acc.y, m);
        acc.z += __shfl_xor_sync(0xffffffffu, acc.z, m);
        acc.w += __shfl_xor_sync(0xffffffffu, acc.w, m);
    }
    // lanes 0 (j 0-3) and 1 (j 4-6) hold the sums; lanes 0-6 write out[n*7+j]
    if (lane < F_OUT) {
        int srcl = lane >> 2;      // 0 or 1
        int comp = lane & 3;
        float cx = __shfl_sync(0x7fu, acc.x, srcl);
        float cy = __shfl_sync(0x7fu, acc.y, srcl);
        float cz = __shfl_sync(0x7fu, acc.z, srcl);
        float cw = __shfl_sync(0x7fu, acc.w, srcl);
        float v = (comp == 0) ? cx : (comp == 1) ? cy : (comp == 2) ? cz : cw;
        out[(size_t)gw * F_OUT + lane] = fmaf(v, g_nd[gw], b2[lane]);
    }
}

// ---------------- launch ------------------------------------------------------
extern "C" void kernel_launch(void* const* d_in, const int* in_sizes, int n_in,
                              void* d_out, int out_size) {
    const float* X   = (const float*)d_in[0];
    const int*   src = (const int*)  d_in[1];
    const int*   dst = (const int*)  d_in[2];
    const float* W1  = (const float*)d_in[3];
    const float* b1  = (const float*)d_in[4];
    const float* W2  = (const float*)d_in[5];
    const float* b2  = (const float*)d_in[6];
    float* out = (float*)d_out;

    const int g1_smem = 8 * KPAD * 8;   // 98304 bytes
    static int attr_done = 0;
    if (!attr_done) {   // idempotent host-side attribute, not a capture op
        cudaFuncSetAttribute(gemm1_kernel,
                             cudaFuncAttributeMaxDynamicSharedMemorySize, g1_smem);
        attr_done = 1;
    }

    zero_kernel       <<<(N_NODES + 255) / 256, 256>>>();
    degree_kernel     <<<N_EDGES / 256, 256>>>(src, dst);
    norm_offset_kernel<<<(N_NODES + 255) / 256, 256>>>();
    place_kernel      <<<N_EDGES / 256, 256>>>(src, dst);
    gemm1_kernel      <<<G1_GRID, 256, g1_smem>>>(X, W1);
    agg1_kernel       <<<N_NODES / 8, 256>>>();
    gemm2_kernel      <<<(N_NODES + 255) / 256, 256>>>(b1, W2);
    agg2_final_kernel <<<N_NODES / 8, 256>>>(b2, out);
}